// round 15
// baseline (speedup 1.0000x reference)
#include <cuda_runtime.h>
#include <cuda_bf16.h>
#include <cuda_fp16.h>
#include <cstdint>
#include <math.h>

// ---------------- problem constants ----------------
#define BB 2
#define SS 2048
#define DD 1024
#define HH 16
#define DHD 64
#define MM (BB*SS)      // 4096

// ---------------- GEMM constants (verified R4/R7 geometry) -----------------
#define KFP 1024
#define KC 32
#define NSTG 4
#define A_STG 8192
#define STG_BYTES (2*A_STG)
#define GEMM_SMEM (NSTG*STG_BYTES)  // 65536

// ---------------- scratch ----------------
__device__ __half g_qh16[BB*HH*SS*DHD];
__device__ __half g_kh16[BB*HH*SS*DHD];
__device__ __half g_vh16[BB*HH*SS*DHD];

__device__ __half g_qa16[(size_t)MM*KFP];
__device__ __half g_ka16[(size_t)MM*KFP];
__device__ __half g_va16[(size_t)MM*KFP];
__device__ __half g_wq16[(size_t)DD*KFP];
__device__ __half g_wk16[(size_t)DD*KFP];
__device__ __half g_wv16[(size_t)DD*KFP];
__device__ __half g_wo16[(size_t)DD*KFP];

__device__ __half g_o16[(size_t)MM*KFP];

// ---------------- PTX helpers ----------------
__device__ __forceinline__ uint32_t smem_u32(const void* p) {
    uint32_t a;
    asm("{ .reg .u64 t; cvta.to.shared.u64 t, %1; cvt.u32.u64 %0, t; }"
        : "=r"(a) : "l"(p));
    return a;
}

#define CP_ASYNC16(dst, src) \
    asm volatile("cp.async.cg.shared.global [%0], [%1], 16;" :: "r"(dst), "l"(src))
#define CP_COMMIT() asm volatile("cp.async.commit_group;" ::: "memory")
#define CP_WAIT2()  asm volatile("cp.async.wait_group 2;" ::: "memory")

#define LDSM4(r0, r1, r2, r3, addr) \
    asm volatile("ldmatrix.sync.aligned.m8n8.x4.shared.b16 {%0,%1,%2,%3}, [%4];" \
        : "=r"(r0), "=r"(r1), "=r"(r2), "=r"(r3) : "r"(addr))
#define LDSM4T(r0, r1, r2, r3, addr) \
    asm volatile("ldmatrix.sync.aligned.m8n8.x4.trans.shared.b16 {%0,%1,%2,%3}, [%4];" \
        : "=r"(r0), "=r"(r1), "=r"(r2), "=r"(r3) : "r"(addr))

#define MMAF16A(c, a, b) \
    asm volatile("mma.sync.aligned.m16n8k16.row.col.f32.f16.f16.f32 " \
        "{%0,%1,%2,%3}, {%4,%5,%6,%7}, {%8,%9}, {%0,%1,%2,%3};" \
        : "+f"((c)[0]), "+f"((c)[1]), "+f"((c)[2]), "+f"((c)[3]) \
        : "r"((a)[0]), "r"((a)[1]), "r"((a)[2]), "r"((a)[3]), \
          "r"((b)[0]), "r"((b)[1]))

#define MMAFP16(c, a0, a1, a2, a3, b0, b1) \
    asm volatile("mma.sync.aligned.m16n8k16.row.col.f32.f16.f16.f32 " \
        "{%0,%1,%2,%3}, {%4,%5,%6,%7}, {%8,%9}, {%0,%1,%2,%3};" \
        : "+f"((c)[0]), "+f"((c)[1]), "+f"((c)[2]), "+f"((c)[3]) \
        : "r"(a0), "r"(a1), "r"(a2), "r"(a3), "r"(b0), "r"(b1))

#define EX2H2(r) asm("ex2.approx.f16x2 %0, %0;" : "+r"(r))

// swizzles (verified)
__device__ __forceinline__ uint32_t swz(int row, int g) {
    return (uint32_t)(row * 64 + ((g ^ ((row >> 1) & 3)) * 16));
}
__device__ __forceinline__ uint32_t swz8(int row, int g) {
    return (uint32_t)(row * 128 + ((g ^ (row & 7)) << 4));
}

// ---------------------------------------------------------------------------
// cvt16x3 / cvt16x4
// ---------------------------------------------------------------------------
__device__ __forceinline__ void cvt16_body(const float4* X, __half* Y, int e) {
    float4 x = X[e];
    __half2 h0 = __floats2half2_rn(x.x, x.y);
    __half2 h1 = __floats2half2_rn(x.z, x.w);
    __half2* y = (__half2*)(Y + (size_t)e * 4);
    y[0] = h0; y[1] = h1;
}

__global__ void __launch_bounds__(256) cvt16x3(const float4* X0, const float4* X1,
                                               const float4* X2,
                                               __half* Y0, __half* Y1, __half* Y2)
{
    const float4* X = (blockIdx.y == 0) ? X0 : (blockIdx.y == 1) ? X1 : X2;
    __half* Y = (blockIdx.y == 0) ? Y0 : (blockIdx.y == 1) ? Y1 : Y2;
    cvt16_body(X, Y, blockIdx.x * 256 + threadIdx.x);
}

__global__ void __launch_bounds__(256) cvt16x4(const float4* X0, const float4* X1,
                                               const float4* X2, const float4* X3,
                                               __half* Y0, __half* Y1,
                                               __half* Y2, __half* Y3)
{
    const float4* X = (blockIdx.y == 0) ? X0 : (blockIdx.y == 1) ? X1
                     : (blockIdx.y == 2) ? X2 : X3;
    __half* Y = (blockIdx.y == 0) ? Y0 : (blockIdx.y == 1) ? Y1
              : (blockIdx.y == 2) ? Y2 : Y3;
    cvt16_body(X, Y, blockIdx.x * 256 + threadIdx.x);
}

// ---------------------------------------------------------------------------
// VERIFIED GEMM core: fp16, K=1024 (unchanged from R11/R13).
// ---------------------------------------------------------------------------
__device__ __forceinline__ void gemm_core16(const char* __restrict__ gA,
                                            const char* __restrict__ gB,
                                            uint32_t sb, float cfr[4][4][4])
{
    const int NCHUNK = KFP / KC;
    const int tid  = threadIdx.x;
    const int lane = tid & 31;
    const int wid  = tid >> 5;
    const int wm   = (wid & 1) * 64;
    const int wn   = (wid >> 1) * 32;

    #pragma unroll
    for (int i = 0; i < 4; i++)
        #pragma unroll
        for (int j = 0; j < 4; j++)
            #pragma unroll
            for (int e = 0; e < 4; e++) cfr[i][j][e] = 0.f;

    int l_isB[4];
    uint32_t l_soff[4];
    size_t l_goff[4];
    #pragma unroll
    for (int i = 0; i < 4; i++) {
        int G = tid + i * 256;
        l_isB[i] = G >> 9;
        int g = G & 511;
        int row = g >> 2;
        int q = g & 3;
        l_soff[i] = (l_isB[i] ? A_STG : 0u) + swz(row, q);
        l_goff[i] = (size_t)row * (KFP * 2) + q * 16;
    }

    #pragma unroll
    for (int s = 0; s < NSTG - 1; s++) {
        const uint32_t st = sb + s * STG_BYTES;
        #pragma unroll
        for (int i = 0; i < 4; i++) {
            const char* src = (l_isB[i] ? gB : gA) + l_goff[i] + (size_t)s * (KC * 2);
            CP_ASYNC16(st + l_soff[i], src);
        }
        CP_COMMIT();
    }

    const int a_row = lane & 15;
    const int a_kg  = lane >> 4;
    const int b_j   = lane >> 4;
    const int b_half= (lane >> 3) & 1;
    const int b_row = lane & 7;

    #pragma unroll 1
    for (int c = 0; c < NCHUNK; c++) {
        CP_WAIT2();
        __syncthreads();

        if (c + NSTG - 1 < NCHUNK) {
            const uint32_t st = sb + ((c + NSTG - 1) & (NSTG - 1)) * STG_BYTES;
            #pragma unroll
            for (int i = 0; i < 4; i++) {
                const char* src = (l_isB[i] ? gB : gA) + l_goff[i]
                                + (size_t)(c + NSTG - 1) * (KC * 2);
                CP_ASYNC16(st + l_soff[i], src);
            }
        }
        CP_COMMIT();

        const uint32_t sA = sb + (c & (NSTG - 1)) * STG_BYTES;
        const uint32_t sBs = sA + A_STG;

        #pragma unroll
        for (int ks = 0; ks < 2; ks++) {
            uint32_t a[4][4];
            #pragma unroll
            for (int mt = 0; mt < 4; mt++) {
                int row = wm + mt * 16 + a_row;
                int kg  = ks * 2 + a_kg;
                LDSM4(a[mt][0], a[mt][1], a[mt][2], a[mt][3], sA + swz(row, kg));
            }
            uint32_t b[4][2];
            #pragma unroll
            for (int pr = 0; pr < 2; pr++) {
                int row = wn + (pr * 2 + b_j) * 8 + b_row;
                int kg  = ks * 2 + b_half;
                uint32_t r0, r1, r2, r3;
                LDSM4(r0, r1, r2, r3, sBs + swz(row, kg));
                b[pr*2][0] = r0; b[pr*2][1] = r1;
                b[pr*2+1][0] = r2; b[pr*2+1][1] = r3;
            }
            #pragma unroll
            for (int mt = 0; mt < 4; mt++)
                #pragma unroll
                for (int nt = 0; nt < 4; nt++)
                    MMAF16A(cfr[mt][nt], a[mt], b[nt]);
        }
        __syncthreads();
    }
}

// Fused QKV projection, fp16 single-pass.
__global__ void __launch_bounds__(256) gemm_qkv16(float qscale)
{
    extern __shared__ char dsm[];
    const uint32_t sb = smem_u32(dsm);

    const int seg = blockIdx.x >> 3;
    const int bn  = (blockIdx.x & 7) * 128;
    const int bm  = blockIdx.y * 128;

    const __half* A = (seg == 0) ? g_qa16 : (seg == 1) ? g_ka16 : g_va16;
    const __half* W = (seg == 0) ? g_wq16 : (seg == 1) ? g_wk16 : g_wv16;
    __half* Hout    = (seg == 0) ? g_qh16 : (seg == 1) ? g_kh16 : g_vh16;
    const float scale = (seg == 0) ? qscale : 1.0f;

    float cfr[4][4][4];
    gemm_core16((const char*)(A + (size_t)bm * KFP),
                (const char*)(W + (size_t)bn * KFP), sb, cfr);

    const int lane = threadIdx.x & 31;
    const int wid  = threadIdx.x >> 5;
    const int wm   = (wid & 1) * 64;
    const int wn   = (wid >> 1) * 32;
    const int r0   = lane >> 2;
    const int cc0  = (lane & 3) * 2;
    #pragma unroll
    for (int mt = 0; mt < 4; mt++) {
        #pragma unroll
        for (int nt = 0; nt < 4; nt++) {
            int m = bm + wm + mt * 16 + r0;
            int n = bn + wn + nt * 8 + cc0;
            int bb = m >> 11, s = m & 2047, h = n >> 6, dh = n & 63;
            __half* d0 = Hout + (((size_t)(bb * HH + h) * SS + s) * DHD + dh);
            *(__half2*)d0 = __floats2half2_rn(cfr[mt][nt][0]*scale, cfr[mt][nt][1]*scale);
            *(__half2*)(d0 + 8 * DHD) = __floats2half2_rn(cfr[mt][nt][2]*scale, cfr[mt][nt][3]*scale);
        }
    }
}

// O-projection, fp16 single-pass, flat f32 out.
__global__ void __launch_bounds__(256) gemm_out16(float* __restrict__ f32dst)
{
    extern __shared__ char dsm[];
    const uint32_t sb = smem_u32(dsm);

    const int bn = blockIdx.x * 128;
    const int bm = blockIdx.y * 128;

    float cfr[4][4][4];
    gemm_core16((const char*)(g_o16 + (size_t)bm * KFP),
                (const char*)(g_wo16 + (size_t)bn * KFP), sb, cfr);

    const int lane = threadIdx.x & 31;
    const int wid  = threadIdx.x >> 5;
    const int wm   = (wid & 1) * 64;
    const int wn   = (wid >> 1) * 32;
    const int r0   = lane >> 2;
    const int cc0  = (lane & 3) * 2;
    #pragma unroll
    for (int mt = 0; mt < 4; mt++) {
        #pragma unroll
        for (int nt = 0; nt < 4; nt++) {
            int m = bm + wm + mt * 16 + r0;
            int n = bn + wn + nt * 8 + cc0;
            float* d0 = f32dst + (size_t)m * DD + n;
            *(float2*)d0 = make_float2(cfr[mt][nt][0], cfr[mt][nt][1]);
            *(float2*)(d0 + 8 * DD) = make_float2(cfr[mt][nt][2], cfr[mt][nt][3]);
        }
    }
}

// ---------------------------------------------------------------------------
// Tensor-core flash attention — R14 structure (4 warps x 32 rows), with:
//  * row sums on the idle FMA pipe (f32 unpack+FADD, R12-verified numerics)
//  * __launch_bounds__(128, 3): 3 CTAs/SM for latency hiding
// ---------------------------------------------------------------------------
#define AT_NIT (SS/64)
#define AT_KV_STG 16384
#define ATTN_SMEM (16384 + 3*AT_KV_STG)   // 65536
#define AT_THREADS 128

__global__ void __launch_bounds__(AT_THREADS, 3) attn_mma()
{
    extern __shared__ char smA[];
    const uint32_t sQ  = smem_u32(smA);
    const uint32_t sKV = sQ + 16384;

    const int tid  = threadIdx.x;
    const int lane = tid & 31;
    const int wrp  = tid >> 5;
    const int bh   = blockIdx.y;
    const int qm0  = blockIdx.x * 128;

    const char* Qg = (const char*)g_qh16 + ((size_t)bh * SS + qm0) * 128;
    const char* Kg = (const char*)g_kh16 + (size_t)bh * SS * 128;
    const char* Vg = (const char*)g_vh16 + (size_t)bh * SS * 128;

    int kv_isV[8], kv_row[8], kv_g[8];
    #pragma unroll
    for (int i = 0; i < 8; i++) {
        int G = tid + i * AT_THREADS;
        kv_isV[i] = G >> 9;
        int g = G & 511;
        kv_row[i] = g >> 3;
        kv_g[i]   = g & 7;
    }

    #pragma unroll
    for (int i = 0; i < 8; i++) {
        int G = tid + i * AT_THREADS;
        int r = G >> 3, g = G & 7;
        CP_ASYNC16(sQ + swz8(r, g), Qg + r * 128 + g * 16);
    }
    #pragma unroll
    for (int i = 0; i < 8; i++) {
        uint32_t dst = sKV + (kv_isV[i] ? 8192u : 0u) + swz8(kv_row[i], kv_g[i]);
        const char* src = (kv_isV[i] ? Vg : Kg) + (size_t)kv_row[i] * 128 + kv_g[i] * 16;
        CP_ASYNC16(dst, src);
    }
    CP_COMMIT();
    #pragma unroll
    for (int i = 0; i < 8; i++) {
        uint32_t dst = sKV + AT_KV_STG + (kv_isV[i] ? 8192u : 0u) + swz8(kv_row[i], kv_g[i]);
        const char* src = (kv_isV[i] ? Vg : Kg) + (size_t)(64 + kv_row[i]) * 128 + kv_g[i] * 16;
        CP_ASYNC16(dst, src);
    }
    CP_COMMIT();

    uint32_t qa[2][4][4];
    float oacc[2][8][4];
    #pragma unroll
    for (int mt = 0; mt < 2; mt++)
        #pragma unroll
        for (int nt = 0; nt < 8; nt++)
            #pragma unroll
            for (int j = 0; j < 4; j++) oacc[mt][nt][j] = 0.f;
    float li[2][2] = {{0.f, 0.f}, {0.f, 0.f}};   // [mt][row-group] partials

    const int aq_row0 = wrp * 32 + (lane & 15);
    const int aq_kg   = lane >> 4;
    const int kb_sub  = lane >> 4;
    const int kb_half = (lane >> 3) & 1;
    const int kb_row  = lane & 7;
    const int vb_rsub = (lane >> 3) & 1;
    const int vb_row  = lane & 7;
    const int vb_gsub = lane >> 4;

    #pragma unroll 1
    for (int it = 0; it < AT_NIT; it++) {
        __syncthreads();
        if (it + 2 < AT_NIT) {
            const uint32_t st = sKV + ((it + 2) % 3) * AT_KV_STG;
            #pragma unroll
            for (int i = 0; i < 8; i++) {
                uint32_t dst = st + (kv_isV[i] ? 8192u : 0u) + swz8(kv_row[i], kv_g[i]);
                const char* src = (kv_isV[i] ? Vg : Kg)
                                + (size_t)((it + 2) * 64 + kv_row[i]) * 128 + kv_g[i] * 16;
                CP_ASYNC16(dst, src);
            }
        }
        CP_COMMIT();
        CP_WAIT2();
        __syncthreads();

        if (it == 0) {
            #pragma unroll
            for (int mt = 0; mt < 2; mt++)
                #pragma unroll
                for (int ks = 0; ks < 4; ks++)
                    LDSM4(qa[mt][ks][0], qa[mt][ks][1], qa[mt][ks][2], qa[mt][ks][3],
                          sQ + swz8(aq_row0 + mt * 16, ks * 2 + aq_kg));
        }

        const uint32_t sK = sKV + (it % 3) * AT_KV_STG;
        const uint32_t sV = sK + 8192;

        // ---- scores = Q @ K^T ----
        float sc[2][8][4];
        #pragma unroll
        for (int mt = 0; mt < 2; mt++)
            #pragma unroll
            for (int nt = 0; nt < 8; nt++)
                #pragma unroll
                for (int j = 0; j < 4; j++) sc[mt][nt][j] = 0.f;

        #pragma unroll
        for (int ks = 0; ks < 4; ks++) {
            #pragma unroll
            for (int pr = 0; pr < 4; pr++) {
                int row = (pr * 2 + kb_sub) * 8 + kb_row;
                uint32_t b0, b1, b2, b3;
                LDSM4(b0, b1, b2, b3, sK + swz8(row, ks * 2 + kb_half));
                #pragma unroll
                for (int mt = 0; mt < 2; mt++) {
                    MMAFP16(sc[mt][pr*2],   qa[mt][ks][0], qa[mt][ks][1],
                            qa[mt][ks][2], qa[mt][ks][3], b0, b1);
                    MMAFP16(sc[mt][pr*2+1], qa[mt][ks][0], qa[mt][ks][1],
                            qa[mt][ks][2], qa[mt][ks][3], b2, b3);
                }
            }
        }

        // ---- softmax: fp16x2 EX2; row sums accumulated on FMA pipe ----
        uint32_t pa[2][4][4];
        #pragma unroll
        for (int mt = 0; mt < 2; mt++) {
            #pragma unroll
            for (int ks = 0; ks < 4; ks++) {
                __half2 h0 = __floats2half2_rn(sc[mt][2*ks][0],   sc[mt][2*ks][1]);
                __half2 h1 = __floats2half2_rn(sc[mt][2*ks][2],   sc[mt][2*ks][3]);
                __half2 h2 = __floats2half2_rn(sc[mt][2*ks+1][0], sc[mt][2*ks+1][1]);
                __half2 h3 = __floats2half2_rn(sc[mt][2*ks+1][2], sc[mt][2*ks+1][3]);
                pa[mt][ks][0] = *(uint32_t*)&h0; pa[mt][ks][1] = *(uint32_t*)&h1;
                pa[mt][ks][2] = *(uint32_t*)&h2; pa[mt][ks][3] = *(uint32_t*)&h3;
                EX2H2(pa[mt][ks][0]); EX2H2(pa[mt][ks][1]);
                EX2H2(pa[mt][ks][2]); EX2H2(pa[mt][ks][3]);
                // f32 partial sums (exact unpack; FMA pipe, which is idle)
                float2 f0 = __half22float2(*(__half2*)&pa[mt][ks][0]);
                float2 f1 = __half22float2(*(__half2*)&pa[mt][ks][1]);
                float2 f2 = __half22float2(*(__half2*)&pa[mt][ks][2]);
                float2 f3 = __half22float2(*(__half2*)&pa[mt][ks][3]);
                li[mt][0] += (f0.x + f0.y) + (f2.x + f2.y);   // row r
                li[mt][1] += (f1.x + f1.y) + (f3.x + f3.y);   // row r+8
            }
        }

        // ---- O += P @ V ----
        #pragma unroll
        for (int ks = 0; ks < 4; ks++) {
            #pragma unroll
            for (int pr = 0; pr < 4; pr++) {
                int row = ks * 16 + vb_rsub * 8 + vb_row;
                int g   = pr * 2 + vb_gsub;
                uint32_t b0, b1, b2, b3;
                LDSM4T(b0, b1, b2, b3, sV + swz8(row, g));
                #pragma unroll
                for (int mt = 0; mt < 2; mt++) {
                    MMAFP16(oacc[mt][pr*2],   pa[mt][ks][0], pa[mt][ks][1],
                            pa[mt][ks][2], pa[mt][ks][3], b0, b1);
                    MMAFP16(oacc[mt][pr*2+1], pa[mt][ks][0], pa[mt][ks][1],
                            pa[mt][ks][2], pa[mt][ks][3], b2, b3);
                }
            }
        }
    }

    // ---- end-of-loop quad reductions (R12-verified pattern) ----
    #pragma unroll
    for (int mt = 0; mt < 2; mt++) {
        li[mt][0] += __shfl_xor_sync(0xffffffffu, li[mt][0], 1);
        li[mt][0] += __shfl_xor_sync(0xffffffffu, li[mt][0], 2);
        li[mt][1] += __shfl_xor_sync(0xffffffffu, li[mt][1], 1);
        li[mt][1] += __shfl_xor_sync(0xffffffffu, li[mt][1], 2);
    }

    // ---- epilogue: normalize, write fp16 flat [m, 1024] ----
    const int b = bh >> 4;
    const int h = bh & 15;
    const int cbase = h * DHD + (lane & 3) * 2;
    #pragma unroll
    for (int mt = 0; mt < 2; mt++) {
        const float inv0 = 1.0f / li[mt][0], inv1 = 1.0f / li[mt][1];
        const int m_r0 = qm0 + wrp * 32 + mt * 16 + (lane >> 2);
        __half* o0 = g_o16 + ((size_t)(b * SS + m_r0)) * KFP + cbase;
        __half* o1 = o0 + (size_t)8 * KFP;
        #pragma unroll
        for (int nt = 0; nt < 8; nt++) {
            *(__half2*)(o0 + nt * 8) =
                __floats2half2_rn(oacc[mt][nt][0] * inv0, oacc[mt][nt][1] * inv0);
            *(__half2*)(o1 + nt * 8) =
                __floats2half2_rn(oacc[mt][nt][2] * inv1, oacc[mt][nt][3] * inv1);
        }
    }
}

// ---------------------------------------------------------------------------
extern "C" void kernel_launch(void* const* d_in, const int* in_sizes, int n_in,
                              void* d_out, int out_size)
{
    const float* q  = (const float*)d_in[0];
    const float* k  = (const float*)d_in[1];
    const float* v  = (const float*)d_in[2];
    const float* Wq = (const float*)d_in[3];
    const float* Wk = (const float*)d_in[4];
    const float* Wv = (const float*)d_in[5];
    const float* Wo = (const float*)d_in[6];
    float* out = (float*)d_out;

    __half *qa16, *ka16, *va16, *wq16, *wk16, *wv16, *wo16;
    cudaGetSymbolAddress((void**)&qa16, g_qa16);
    cudaGetSymbolAddress((void**)&ka16, g_ka16);
    cudaGetSymbolAddress((void**)&va16, g_va16);
    cudaGetSymbolAddress((void**)&wq16, g_wq16);
    cudaGetSymbolAddress((void**)&wk16, g_wk16);
    cudaGetSymbolAddress((void**)&wv16, g_wv16);
    cudaGetSymbolAddress((void**)&wo16, g_wo16);

    cudaFuncSetAttribute(gemm_qkv16, cudaFuncAttributeMaxDynamicSharedMemorySize, GEMM_SMEM);
    cudaFuncSetAttribute(gemm_out16, cudaFuncAttributeMaxDynamicSharedMemorySize, GEMM_SMEM);
    cudaFuncSetAttribute(attn_mma, cudaFuncAttributeMaxDynamicSharedMemorySize, ATTN_SMEM);

    dim3 ca(MM, 3), cw(DD, 4);
    cvt16x3<<<ca, 256>>>((const float4*)q, (const float4*)k, (const float4*)v,
                         qa16, ka16, va16);
    cvt16x4<<<cw, 256>>>((const float4*)Wq, (const float4*)Wk,
                         (const float4*)Wv, (const float4*)Wo,
                         wq16, wk16, wv16, wo16);

    const float qscale = 0.125f * 1.44269504f;
    dim3 gqkv(24, MM / 128);
    gemm_qkv16<<<gqkv, 256, GEMM_SMEM>>>(qscale);

    dim3 ga(SS / 128, BB * HH);
    attn_mma<<<ga, AT_THREADS, ATTN_SMEM>>>();

    dim3 go(DD / 128, MM / 128);
    gemm_out16<<<go, 256, GEMM_SMEM>>>(out);
}

// round 16
// speedup vs baseline: 1.0387x; 1.0387x over previous
#include <cuda_runtime.h>
#include <cuda_bf16.h>
#include <cuda_fp16.h>
#include <cstdint>
#include <math.h>

// ---------------- problem constants ----------------
#define BB 2
#define SS 2048
#define DD 1024
#define HH 16
#define DHD 64
#define MM (BB*SS)      // 4096

// ---------------- GEMM constants (verified R4/R7 geometry) -----------------
#define KFP 1024
#define KC 32
#define NSTG 4
#define A_STG 8192
#define STG_BYTES (2*A_STG)
#define GEMM_SMEM (NSTG*STG_BYTES)  // 65536

// ---------------- scratch ----------------
__device__ __half g_qh16[BB*HH*SS*DHD];
__device__ __half g_kh16[BB*HH*SS*DHD];
__device__ __half g_vh16[BB*HH*SS*DHD];

__device__ __half g_qa16[(size_t)MM*KFP];
__device__ __half g_ka16[(size_t)MM*KFP];
__device__ __half g_va16[(size_t)MM*KFP];
__device__ __half g_wq16[(size_t)DD*KFP];
__device__ __half g_wk16[(size_t)DD*KFP];
__device__ __half g_wv16[(size_t)DD*KFP];
__device__ __half g_wo16[(size_t)DD*KFP];

__device__ __half g_o16[(size_t)MM*KFP];

// ---------------- PTX helpers ----------------
__device__ __forceinline__ uint32_t smem_u32(const void* p) {
    uint32_t a;
    asm("{ .reg .u64 t; cvta.to.shared.u64 t, %1; cvt.u32.u64 %0, t; }"
        : "=r"(a) : "l"(p));
    return a;
}

#define CP_ASYNC16(dst, src) \
    asm volatile("cp.async.cg.shared.global [%0], [%1], 16;" :: "r"(dst), "l"(src))
#define CP_COMMIT() asm volatile("cp.async.commit_group;" ::: "memory")
#define CP_WAIT2()  asm volatile("cp.async.wait_group 2;" ::: "memory")

#define LDSM4(r0, r1, r2, r3, addr) \
    asm volatile("ldmatrix.sync.aligned.m8n8.x4.shared.b16 {%0,%1,%2,%3}, [%4];" \
        : "=r"(r0), "=r"(r1), "=r"(r2), "=r"(r3) : "r"(addr))
#define LDSM4T(r0, r1, r2, r3, addr) \
    asm volatile("ldmatrix.sync.aligned.m8n8.x4.trans.shared.b16 {%0,%1,%2,%3}, [%4];" \
        : "=r"(r0), "=r"(r1), "=r"(r2), "=r"(r3) : "r"(addr))

#define MMAF16A(c, a, b) \
    asm volatile("mma.sync.aligned.m16n8k16.row.col.f32.f16.f16.f32 " \
        "{%0,%1,%2,%3}, {%4,%5,%6,%7}, {%8,%9}, {%0,%1,%2,%3};" \
        : "+f"((c)[0]), "+f"((c)[1]), "+f"((c)[2]), "+f"((c)[3]) \
        : "r"((a)[0]), "r"((a)[1]), "r"((a)[2]), "r"((a)[3]), \
          "r"((b)[0]), "r"((b)[1]))

#define MMAFP16(c, a0, a1, a2, a3, b0, b1) \
    asm volatile("mma.sync.aligned.m16n8k16.row.col.f32.f16.f16.f32 " \
        "{%0,%1,%2,%3}, {%4,%5,%6,%7}, {%8,%9}, {%0,%1,%2,%3};" \
        : "+f"((c)[0]), "+f"((c)[1]), "+f"((c)[2]), "+f"((c)[3]) \
        : "r"(a0), "r"(a1), "r"(a2), "r"(a3), "r"(b0), "r"(b1))

#define EX2H2(r) asm("ex2.approx.f16x2 %0, %0;" : "+r"(r))

// swizzles (verified)
__device__ __forceinline__ uint32_t swz(int row, int g) {
    return (uint32_t)(row * 64 + ((g ^ ((row >> 1) & 3)) * 16));
}
__device__ __forceinline__ uint32_t swz8(int row, int g) {
    return (uint32_t)(row * 128 + ((g ^ (row & 7)) << 4));
}

// ---------------------------------------------------------------------------
// cvt16x3 / cvt16x4
// ---------------------------------------------------------------------------
__device__ __forceinline__ void cvt16_body(const float4* X, __half* Y, int e) {
    float4 x = X[e];
    __half2 h0 = __floats2half2_rn(x.x, x.y);
    __half2 h1 = __floats2half2_rn(x.z, x.w);
    __half2* y = (__half2*)(Y + (size_t)e * 4);
    y[0] = h0; y[1] = h1;
}

__global__ void __launch_bounds__(256) cvt16x3(const float4* X0, const float4* X1,
                                               const float4* X2,
                                               __half* Y0, __half* Y1, __half* Y2)
{
    const float4* X = (blockIdx.y == 0) ? X0 : (blockIdx.y == 1) ? X1 : X2;
    __half* Y = (blockIdx.y == 0) ? Y0 : (blockIdx.y == 1) ? Y1 : Y2;
    cvt16_body(X, Y, blockIdx.x * 256 + threadIdx.x);
}

__global__ void __launch_bounds__(256) cvt16x4(const float4* X0, const float4* X1,
                                               const float4* X2, const float4* X3,
                                               __half* Y0, __half* Y1,
                                               __half* Y2, __half* Y3)
{
    const float4* X = (blockIdx.y == 0) ? X0 : (blockIdx.y == 1) ? X1
                     : (blockIdx.y == 2) ? X2 : X3;
    __half* Y = (blockIdx.y == 0) ? Y0 : (blockIdx.y == 1) ? Y1
              : (blockIdx.y == 2) ? Y2 : Y3;
    cvt16_body(X, Y, blockIdx.x * 256 + threadIdx.x);
}

// ---------------------------------------------------------------------------
// VERIFIED GEMM core: fp16, K=1024 (unchanged R11/R13).
// ---------------------------------------------------------------------------
__device__ __forceinline__ void gemm_core16(const char* __restrict__ gA,
                                            const char* __restrict__ gB,
                                            uint32_t sb, float cfr[4][4][4])
{
    const int NCHUNK = KFP / KC;
    const int tid  = threadIdx.x;
    const int lane = tid & 31;
    const int wid  = tid >> 5;
    const int wm   = (wid & 1) * 64;
    const int wn   = (wid >> 1) * 32;

    #pragma unroll
    for (int i = 0; i < 4; i++)
        #pragma unroll
        for (int j = 0; j < 4; j++)
            #pragma unroll
            for (int e = 0; e < 4; e++) cfr[i][j][e] = 0.f;

    int l_isB[4];
    uint32_t l_soff[4];
    size_t l_goff[4];
    #pragma unroll
    for (int i = 0; i < 4; i++) {
        int G = tid + i * 256;
        l_isB[i] = G >> 9;
        int g = G & 511;
        int row = g >> 2;
        int q = g & 3;
        l_soff[i] = (l_isB[i] ? A_STG : 0u) + swz(row, q);
        l_goff[i] = (size_t)row * (KFP * 2) + q * 16;
    }

    #pragma unroll
    for (int s = 0; s < NSTG - 1; s++) {
        const uint32_t st = sb + s * STG_BYTES;
        #pragma unroll
        for (int i = 0; i < 4; i++) {
            const char* src = (l_isB[i] ? gB : gA) + l_goff[i] + (size_t)s * (KC * 2);
            CP_ASYNC16(st + l_soff[i], src);
        }
        CP_COMMIT();
    }

    const int a_row = lane & 15;
    const int a_kg  = lane >> 4;
    const int b_j   = lane >> 4;
    const int b_half= (lane >> 3) & 1;
    const int b_row = lane & 7;

    #pragma unroll 1
    for (int c = 0; c < NCHUNK; c++) {
        CP_WAIT2();
        __syncthreads();

        if (c + NSTG - 1 < NCHUNK) {
            const uint32_t st = sb + ((c + NSTG - 1) & (NSTG - 1)) * STG_BYTES;
            #pragma unroll
            for (int i = 0; i < 4; i++) {
                const char* src = (l_isB[i] ? gB : gA) + l_goff[i]
                                + (size_t)(c + NSTG - 1) * (KC * 2);
                CP_ASYNC16(st + l_soff[i], src);
            }
        }
        CP_COMMIT();

        const uint32_t sA = sb + (c & (NSTG - 1)) * STG_BYTES;
        const uint32_t sBs = sA + A_STG;

        #pragma unroll
        for (int ks = 0; ks < 2; ks++) {
            uint32_t a[4][4];
            #pragma unroll
            for (int mt = 0; mt < 4; mt++) {
                int row = wm + mt * 16 + a_row;
                int kg  = ks * 2 + a_kg;
                LDSM4(a[mt][0], a[mt][1], a[mt][2], a[mt][3], sA + swz(row, kg));
            }
            uint32_t b[4][2];
            #pragma unroll
            for (int pr = 0; pr < 2; pr++) {
                int row = wn + (pr * 2 + b_j) * 8 + b_row;
                int kg  = ks * 2 + b_half;
                uint32_t r0, r1, r2, r3;
                LDSM4(r0, r1, r2, r3, sBs + swz(row, kg));
                b[pr*2][0] = r0; b[pr*2][1] = r1;
                b[pr*2+1][0] = r2; b[pr*2+1][1] = r3;
            }
            #pragma unroll
            for (int mt = 0; mt < 4; mt++)
                #pragma unroll
                for (int nt = 0; nt < 4; nt++)
                    MMAF16A(cfr[mt][nt], a[mt], b[nt]);
        }
        __syncthreads();
    }
}

// Fused QKV projection, fp16 single-pass.
__global__ void __launch_bounds__(256) gemm_qkv16(float qscale)
{
    extern __shared__ char dsm[];
    const uint32_t sb = smem_u32(dsm);

    const int seg = blockIdx.x >> 3;
    const int bn  = (blockIdx.x & 7) * 128;
    const int bm  = blockIdx.y * 128;

    const __half* A = (seg == 0) ? g_qa16 : (seg == 1) ? g_ka16 : g_va16;
    const __half* W = (seg == 0) ? g_wq16 : (seg == 1) ? g_wk16 : g_wv16;
    __half* Hout    = (seg == 0) ? g_qh16 : (seg == 1) ? g_kh16 : g_vh16;
    const float scale = (seg == 0) ? qscale : 1.0f;

    float cfr[4][4][4];
    gemm_core16((const char*)(A + (size_t)bm * KFP),
                (const char*)(W + (size_t)bn * KFP), sb, cfr);

    const int lane = threadIdx.x & 31;
    const int wid  = threadIdx.x >> 5;
    const int wm   = (wid & 1) * 64;
    const int wn   = (wid >> 1) * 32;
    const int r0   = lane >> 2;
    const int cc0  = (lane & 3) * 2;
    #pragma unroll
    for (int mt = 0; mt < 4; mt++) {
        #pragma unroll
        for (int nt = 0; nt < 4; nt++) {
            int m = bm + wm + mt * 16 + r0;
            int n = bn + wn + nt * 8 + cc0;
            int bb = m >> 11, s = m & 2047, h = n >> 6, dh = n & 63;
            __half* d0 = Hout + (((size_t)(bb * HH + h) * SS + s) * DHD + dh);
            *(__half2*)d0 = __floats2half2_rn(cfr[mt][nt][0]*scale, cfr[mt][nt][1]*scale);
            *(__half2*)(d0 + 8 * DHD) = __floats2half2_rn(cfr[mt][nt][2]*scale, cfr[mt][nt][3]*scale);
        }
    }
}

// O-projection, fp16 single-pass, flat f32 out.
__global__ void __launch_bounds__(256) gemm_out16(float* __restrict__ f32dst)
{
    extern __shared__ char dsm[];
    const uint32_t sb = smem_u32(dsm);

    const int bn = blockIdx.x * 128;
    const int bm = blockIdx.y * 128;

    float cfr[4][4][4];
    gemm_core16((const char*)(g_o16 + (size_t)bm * KFP),
                (const char*)(g_wo16 + (size_t)bn * KFP), sb, cfr);

    const int lane = threadIdx.x & 31;
    const int wid  = threadIdx.x >> 5;
    const int wm   = (wid & 1) * 64;
    const int wn   = (wid >> 1) * 32;
    const int r0   = lane >> 2;
    const int cc0  = (lane & 3) * 2;
    #pragma unroll
    for (int mt = 0; mt < 4; mt++) {
        #pragma unroll
        for (int nt = 0; nt < 4; nt++) {
            int m = bm + wm + mt * 16 + r0;
            int n = bn + wn + nt * 8 + cc0;
            float* d0 = f32dst + (size_t)m * DD + n;
            *(float2*)d0 = make_float2(cfr[mt][nt][0], cfr[mt][nt][1]);
            *(float2*)(d0 + 8 * DD) = make_float2(cfr[mt][nt][2], cfr[mt][nt][3]);
        }
    }
}

// ---------------------------------------------------------------------------
// Tensor-core flash attention — R14 body (4 warps x 32 rows, ones-MMA row
// sums) with a 4-STAGE KV ring and ONE barrier per iteration:
//   wait_group 2 (my stage-it copies done) -> __syncthreads (all copies
//   visible; all warps done with iter it-1, last reader of buf (it+3)%4)
//   -> prefetch stage it+3 -> commit -> compute stage it.
// ---------------------------------------------------------------------------
#define AT_NIT (SS/64)
#define AT_KV_STG 16384
#define AT_NBUF 4
#define ATTN_SMEM (16384 + AT_NBUF*AT_KV_STG)   // 81920
#define AT_THREADS 128

__global__ void __launch_bounds__(AT_THREADS) attn_mma()
{
    extern __shared__ char smA[];
    const uint32_t sQ  = smem_u32(smA);
    const uint32_t sKV = sQ + 16384;

    const int tid  = threadIdx.x;
    const int lane = tid & 31;
    const int wrp  = tid >> 5;
    const int bh   = blockIdx.y;
    const int qm0  = blockIdx.x * 128;

    const char* Qg = (const char*)g_qh16 + ((size_t)bh * SS + qm0) * 128;
    const char* Kg = (const char*)g_kh16 + (size_t)bh * SS * 128;
    const char* Vg = (const char*)g_vh16 + (size_t)bh * SS * 128;

    int kv_isV[8], kv_row[8], kv_g[8];
    #pragma unroll
    for (int i = 0; i < 8; i++) {
        int G = tid + i * AT_THREADS;
        kv_isV[i] = G >> 9;
        int g = G & 511;
        kv_row[i] = g >> 3;
        kv_g[i]   = g & 7;
    }

    // prologue: group0 = Q + KV stage 0; group1 = stage 1; group2 = stage 2
    #pragma unroll
    for (int i = 0; i < 8; i++) {
        int G = tid + i * AT_THREADS;
        int r = G >> 3, g = G & 7;
        CP_ASYNC16(sQ + swz8(r, g), Qg + r * 128 + g * 16);
    }
    #pragma unroll
    for (int i = 0; i < 8; i++) {
        uint32_t dst = sKV + (kv_isV[i] ? 8192u : 0u) + swz8(kv_row[i], kv_g[i]);
        const char* src = (kv_isV[i] ? Vg : Kg) + (size_t)kv_row[i] * 128 + kv_g[i] * 16;
        CP_ASYNC16(dst, src);
    }
    CP_COMMIT();
    #pragma unroll
    for (int s = 1; s < 3; s++) {
        #pragma unroll
        for (int i = 0; i < 8; i++) {
            uint32_t dst = sKV + s * AT_KV_STG + (kv_isV[i] ? 8192u : 0u)
                         + swz8(kv_row[i], kv_g[i]);
            const char* src = (kv_isV[i] ? Vg : Kg)
                            + (size_t)(s * 64 + kv_row[i]) * 128 + kv_g[i] * 16;
            CP_ASYNC16(dst, src);
        }
        CP_COMMIT();
    }

    uint32_t qa[2][4][4];
    float oacc[2][8][4];
    #pragma unroll
    for (int mt = 0; mt < 2; mt++)
        #pragma unroll
        for (int nt = 0; nt < 8; nt++)
            #pragma unroll
            for (int j = 0; j < 4; j++) oacc[mt][nt][j] = 0.f;
    float lacc[2][4] = {{0.f,0.f,0.f,0.f},{0.f,0.f,0.f,0.f}};

    const int aq_row0 = wrp * 32 + (lane & 15);
    const int aq_kg   = lane >> 4;
    const int kb_sub  = lane >> 4;
    const int kb_half = (lane >> 3) & 1;
    const int kb_row  = lane & 7;
    const int vb_rsub = (lane >> 3) & 1;
    const int vb_row  = lane & 7;
    const int vb_gsub = lane >> 4;
    const uint32_t HONES = 0x3C003C00u;

    #pragma unroll 1
    for (int it = 0; it < AT_NIT; it++) {
        CP_WAIT2();          // my stage-it copies complete (3 groups pending)
        __syncthreads();     // all copies visible; buf (it+3)%4 free

        // prefetch stage it+3
        if (it + 3 < AT_NIT) {
            const uint32_t st = sKV + ((it + 3) & 3) * AT_KV_STG;
            #pragma unroll
            for (int i = 0; i < 8; i++) {
                uint32_t dst = st + (kv_isV[i] ? 8192u : 0u) + swz8(kv_row[i], kv_g[i]);
                const char* src = (kv_isV[i] ? Vg : Kg)
                                + (size_t)((it + 3) * 64 + kv_row[i]) * 128 + kv_g[i] * 16;
                CP_ASYNC16(dst, src);
            }
        }
        CP_COMMIT();

        if (it == 0) {
            #pragma unroll
            for (int mt = 0; mt < 2; mt++)
                #pragma unroll
                for (int ks = 0; ks < 4; ks++)
                    LDSM4(qa[mt][ks][0], qa[mt][ks][1], qa[mt][ks][2], qa[mt][ks][3],
                          sQ + swz8(aq_row0 + mt * 16, ks * 2 + aq_kg));
        }

        const uint32_t sK = sKV + (it & 3) * AT_KV_STG;
        const uint32_t sV = sK + 8192;

        // ---- scores = Q @ K^T ----
        float sc[2][8][4];
        #pragma unroll
        for (int mt = 0; mt < 2; mt++)
            #pragma unroll
            for (int nt = 0; nt < 8; nt++)
                #pragma unroll
                for (int j = 0; j < 4; j++) sc[mt][nt][j] = 0.f;

        #pragma unroll
        for (int ks = 0; ks < 4; ks++) {
            #pragma unroll
            for (int pr = 0; pr < 4; pr++) {
                int row = (pr * 2 + kb_sub) * 8 + kb_row;
                uint32_t b0, b1, b2, b3;
                LDSM4(b0, b1, b2, b3, sK + swz8(row, ks * 2 + kb_half));
                #pragma unroll
                for (int mt = 0; mt < 2; mt++) {
                    MMAFP16(sc[mt][pr*2],   qa[mt][ks][0], qa[mt][ks][1],
                            qa[mt][ks][2], qa[mt][ks][3], b0, b1);
                    MMAFP16(sc[mt][pr*2+1], qa[mt][ks][0], qa[mt][ks][1],
                            qa[mt][ks][2], qa[mt][ks][3], b2, b3);
                }
            }
        }

        // ---- softmax: fp16x2 EX2 + ones-MMA row sums (R14-verified) ----
        uint32_t pa[2][4][4];
        #pragma unroll
        for (int mt = 0; mt < 2; mt++) {
            #pragma unroll
            for (int ks = 0; ks < 4; ks++) {
                __half2 h0 = __floats2half2_rn(sc[mt][2*ks][0],   sc[mt][2*ks][1]);
                __half2 h1 = __floats2half2_rn(sc[mt][2*ks][2],   sc[mt][2*ks][3]);
                __half2 h2 = __floats2half2_rn(sc[mt][2*ks+1][0], sc[mt][2*ks+1][1]);
                __half2 h3 = __floats2half2_rn(sc[mt][2*ks+1][2], sc[mt][2*ks+1][3]);
                pa[mt][ks][0] = *(uint32_t*)&h0; pa[mt][ks][1] = *(uint32_t*)&h1;
                pa[mt][ks][2] = *(uint32_t*)&h2; pa[mt][ks][3] = *(uint32_t*)&h3;
                EX2H2(pa[mt][ks][0]); EX2H2(pa[mt][ks][1]);
                EX2H2(pa[mt][ks][2]); EX2H2(pa[mt][ks][3]);
                MMAFP16(lacc[mt], pa[mt][ks][0], pa[mt][ks][1],
                        pa[mt][ks][2], pa[mt][ks][3], HONES, HONES);
            }
        }

        // ---- O += P @ V ----
        #pragma unroll
        for (int ks = 0; ks < 4; ks++) {
            #pragma unroll
            for (int pr = 0; pr < 4; pr++) {
                int row = ks * 16 + vb_rsub * 8 + vb_row;
                int g   = pr * 2 + vb_gsub;
                uint32_t b0, b1, b2, b3;
                LDSM4T(b0, b1, b2, b3, sV + swz8(row, g));
                #pragma unroll
                for (int mt = 0; mt < 2; mt++) {
                    MMAFP16(oacc[mt][pr*2],   pa[mt][ks][0], pa[mt][ks][1],
                            pa[mt][ks][2], pa[mt][ks][3], b0, b1);
                    MMAFP16(oacc[mt][pr*2+1], pa[mt][ks][0], pa[mt][ks][1],
                            pa[mt][ks][2], pa[mt][ks][3], b2, b3);
                }
            }
        }
    }

    // ---- epilogue: normalize, write fp16 flat [m, 1024] ----
    const int b = bh >> 4;
    const int h = bh & 15;
    const int cbase = h * DHD + (lane & 3) * 2;
    #pragma unroll
    for (int mt = 0; mt < 2; mt++) {
        const float inv0 = 1.0f / lacc[mt][0], inv1 = 1.0f / lacc[mt][2];
        const int m_r0 = qm0 + wrp * 32 + mt * 16 + (lane >> 2);
        __half* o0 = g_o16 + ((size_t)(b * SS + m_r0)) * KFP + cbase;
        __half* o1 = o0 + (size_t)8 * KFP;
        #pragma unroll
        for (int nt = 0; nt < 8; nt++) {
            *(__half2*)(o0 + nt * 8) =
                __floats2half2_rn(oacc[mt][nt][0] * inv0, oacc[mt][nt][1] * inv0);
            *(__half2*)(o1 + nt * 8) =
                __floats2half2_rn(oacc[mt][nt][2] * inv1, oacc[mt][nt][3] * inv1);
        }
    }
}

// ---------------------------------------------------------------------------
extern "C" void kernel_launch(void* const* d_in, const int* in_sizes, int n_in,
                              void* d_out, int out_size)
{
    const float* q  = (const float*)d_in[0];
    const float* k  = (const float*)d_in[1];
    const float* v  = (const float*)d_in[2];
    const float* Wq = (const float*)d_in[3];
    const float* Wk = (const float*)d_in[4];
    const float* Wv = (const float*)d_in[5];
    const float* Wo = (const float*)d_in[6];
    float* out = (float*)d_out;

    __half *qa16, *ka16, *va16, *wq16, *wk16, *wv16, *wo16;
    cudaGetSymbolAddress((void**)&qa16, g_qa16);
    cudaGetSymbolAddress((void**)&ka16, g_ka16);
    cudaGetSymbolAddress((void**)&va16, g_va16);
    cudaGetSymbolAddress((void**)&wq16, g_wq16);
    cudaGetSymbolAddress((void**)&wk16, g_wk16);
    cudaGetSymbolAddress((void**)&wv16, g_wv16);
    cudaGetSymbolAddress((void**)&wo16, g_wo16);

    cudaFuncSetAttribute(gemm_qkv16, cudaFuncAttributeMaxDynamicSharedMemorySize, GEMM_SMEM);
    cudaFuncSetAttribute(gemm_out16, cudaFuncAttributeMaxDynamicSharedMemorySize, GEMM_SMEM);
    cudaFuncSetAttribute(attn_mma, cudaFuncAttributeMaxDynamicSharedMemorySize, ATTN_SMEM);

    dim3 ca(MM, 3), cw(DD, 4);
    cvt16x3<<<ca, 256>>>((const float4*)q, (const float4*)k, (const float4*)v,
                         qa16, ka16, va16);
    cvt16x4<<<cw, 256>>>((const float4*)Wq, (const float4*)Wk,
                         (const float4*)Wv, (const float4*)Wo,
                         wq16, wk16, wv16, wo16);

    const float qscale = 0.125f * 1.44269504f;
    dim3 gqkv(24, MM / 128);
    gemm_qkv16<<<gqkv, 256, GEMM_SMEM>>>(qscale);

    dim3 ga(SS / 128, BB * HH);
    attn_mma<<<ga, AT_THREADS, ATTN_SMEM>>>();

    dim3 go(DD / 128, MM / 128);
    gemm_out16<<<go, 256, GEMM_SMEM>>>(out);
}

// round 17
// speedup vs baseline: 1.0586x; 1.0192x over previous
#include <cuda_runtime.h>
#include <cuda_bf16.h>
#include <cuda_fp16.h>
#include <cstdint>
#include <math.h>

// ---------------- problem constants ----------------
#define BB 2
#define SS 2048
#define DD 1024
#define HH 16
#define DHD 64
#define MM (BB*SS)      // 4096

// ---------------- GEMM constants (verified R4/R7 geometry) -----------------
#define KFP 1024
#define KC 32
#define NSTG 4
#define A_STG 8192
#define STG_BYTES (2*A_STG)
#define GEMM_SMEM (NSTG*STG_BYTES)  // 65536

// ---------------- scratch ----------------
__device__ __half g_qh16[BB*HH*SS*DHD];
__device__ __half g_kh16[BB*HH*SS*DHD];
__device__ __half g_vh16[BB*HH*SS*DHD];

__device__ __half g_qa16[(size_t)MM*KFP];
__device__ __half g_ka16[(size_t)MM*KFP];
__device__ __half g_va16[(size_t)MM*KFP];
__device__ __half g_wq16[(size_t)DD*KFP];
__device__ __half g_wk16[(size_t)DD*KFP];
__device__ __half g_wv16[(size_t)DD*KFP];
__device__ __half g_wo16[(size_t)DD*KFP];

__device__ __half g_o16[(size_t)MM*KFP];

// ---------------- PTX helpers ----------------
__device__ __forceinline__ uint32_t smem_u32(const void* p) {
    uint32_t a;
    asm("{ .reg .u64 t; cvta.to.shared.u64 t, %1; cvt.u32.u64 %0, t; }"
        : "=r"(a) : "l"(p));
    return a;
}

#define CP_ASYNC16(dst, src) \
    asm volatile("cp.async.cg.shared.global [%0], [%1], 16;" :: "r"(dst), "l"(src))
#define CP_COMMIT() asm volatile("cp.async.commit_group;" ::: "memory")
#define CP_WAIT2()  asm volatile("cp.async.wait_group 2;" ::: "memory")
#define CP_WAIT0()  asm volatile("cp.async.wait_group 0;" ::: "memory")

#define LDSM4(r0, r1, r2, r3, addr) \
    asm volatile("ldmatrix.sync.aligned.m8n8.x4.shared.b16 {%0,%1,%2,%3}, [%4];" \
        : "=r"(r0), "=r"(r1), "=r"(r2), "=r"(r3) : "r"(addr))
#define LDSM4T(r0, r1, r2, r3, addr) \
    asm volatile("ldmatrix.sync.aligned.m8n8.x4.trans.shared.b16 {%0,%1,%2,%3}, [%4];" \
        : "=r"(r0), "=r"(r1), "=r"(r2), "=r"(r3) : "r"(addr))

#define MMAF16A(c, a, b) \
    asm volatile("mma.sync.aligned.m16n8k16.row.col.f32.f16.f16.f32 " \
        "{%0,%1,%2,%3}, {%4,%5,%6,%7}, {%8,%9}, {%0,%1,%2,%3};" \
        : "+f"((c)[0]), "+f"((c)[1]), "+f"((c)[2]), "+f"((c)[3]) \
        : "r"((a)[0]), "r"((a)[1]), "r"((a)[2]), "r"((a)[3]), \
          "r"((b)[0]), "r"((b)[1]))

#define MMAFP16(c, a0, a1, a2, a3, b0, b1) \
    asm volatile("mma.sync.aligned.m16n8k16.row.col.f32.f16.f16.f32 " \
        "{%0,%1,%2,%3}, {%4,%5,%6,%7}, {%8,%9}, {%0,%1,%2,%3};" \
        : "+f"((c)[0]), "+f"((c)[1]), "+f"((c)[2]), "+f"((c)[3]) \
        : "r"(a0), "r"(a1), "r"(a2), "r"(a3), "r"(b0), "r"(b1))

#define EX2H2(r) asm("ex2.approx.f16x2 %0, %0;" : "+r"(r))

// swizzles (verified)
__device__ __forceinline__ uint32_t swz(int row, int g) {
    return (uint32_t)(row * 64 + ((g ^ ((row >> 1) & 3)) * 16));
}
__device__ __forceinline__ uint32_t swz8(int row, int g) {
    return (uint32_t)(row * 128 + ((g ^ (row & 7)) << 4));
}

// ---------------------------------------------------------------------------
// cvt16x3 / cvt16x4
// ---------------------------------------------------------------------------
__device__ __forceinline__ void cvt16_body(const float4* X, __half* Y, int e) {
    float4 x = X[e];
    __half2 h0 = __floats2half2_rn(x.x, x.y);
    __half2 h1 = __floats2half2_rn(x.z, x.w);
    __half2* y = (__half2*)(Y + (size_t)e * 4);
    y[0] = h0; y[1] = h1;
}

__global__ void __launch_bounds__(256) cvt16x3(const float4* X0, const float4* X1,
                                               const float4* X2,
                                               __half* Y0, __half* Y1, __half* Y2)
{
    const float4* X = (blockIdx.y == 0) ? X0 : (blockIdx.y == 1) ? X1 : X2;
    __half* Y = (blockIdx.y == 0) ? Y0 : (blockIdx.y == 1) ? Y1 : Y2;
    cvt16_body(X, Y, blockIdx.x * 256 + threadIdx.x);
}

__global__ void __launch_bounds__(256) cvt16x4(const float4* X0, const float4* X1,
                                               const float4* X2, const float4* X3,
                                               __half* Y0, __half* Y1,
                                               __half* Y2, __half* Y3)
{
    const float4* X = (blockIdx.y == 0) ? X0 : (blockIdx.y == 1) ? X1
                     : (blockIdx.y == 2) ? X2 : X3;
    __half* Y = (blockIdx.y == 0) ? Y0 : (blockIdx.y == 1) ? Y1
              : (blockIdx.y == 2) ? Y2 : Y3;
    cvt16_body(X, Y, blockIdx.x * 256 + threadIdx.x);
}

// ---------------------------------------------------------------------------
// VERIFIED GEMM core: fp16, K=1024 (unchanged R11/R13).
// ---------------------------------------------------------------------------
__device__ __forceinline__ void gemm_core16(const char* __restrict__ gA,
                                            const char* __restrict__ gB,
                                            uint32_t sb, float cfr[4][4][4])
{
    const int NCHUNK = KFP / KC;
    const int tid  = threadIdx.x;
    const int lane = tid & 31;
    const int wid  = tid >> 5;
    const int wm   = (wid & 1) * 64;
    const int wn   = (wid >> 1) * 32;

    #pragma unroll
    for (int i = 0; i < 4; i++)
        #pragma unroll
        for (int j = 0; j < 4; j++)
            #pragma unroll
            for (int e = 0; e < 4; e++) cfr[i][j][e] = 0.f;

    int l_isB[4];
    uint32_t l_soff[4];
    size_t l_goff[4];
    #pragma unroll
    for (int i = 0; i < 4; i++) {
        int G = tid + i * 256;
        l_isB[i] = G >> 9;
        int g = G & 511;
        int row = g >> 2;
        int q = g & 3;
        l_soff[i] = (l_isB[i] ? A_STG : 0u) + swz(row, q);
        l_goff[i] = (size_t)row * (KFP * 2) + q * 16;
    }

    #pragma unroll
    for (int s = 0; s < NSTG - 1; s++) {
        const uint32_t st = sb + s * STG_BYTES;
        #pragma unroll
        for (int i = 0; i < 4; i++) {
            const char* src = (l_isB[i] ? gB : gA) + l_goff[i] + (size_t)s * (KC * 2);
            CP_ASYNC16(st + l_soff[i], src);
        }
        CP_COMMIT();
    }

    const int a_row = lane & 15;
    const int a_kg  = lane >> 4;
    const int b_j   = lane >> 4;
    const int b_half= (lane >> 3) & 1;
    const int b_row = lane & 7;

    #pragma unroll 1
    for (int c = 0; c < NCHUNK; c++) {
        CP_WAIT2();
        __syncthreads();

        if (c + NSTG - 1 < NCHUNK) {
            const uint32_t st = sb + ((c + NSTG - 1) & (NSTG - 1)) * STG_BYTES;
            #pragma unroll
            for (int i = 0; i < 4; i++) {
                const char* src = (l_isB[i] ? gB : gA) + l_goff[i]
                                + (size_t)(c + NSTG - 1) * (KC * 2);
                CP_ASYNC16(st + l_soff[i], src);
            }
        }
        CP_COMMIT();

        const uint32_t sA = sb + (c & (NSTG - 1)) * STG_BYTES;
        const uint32_t sBs = sA + A_STG;

        #pragma unroll
        for (int ks = 0; ks < 2; ks++) {
            uint32_t a[4][4];
            #pragma unroll
            for (int mt = 0; mt < 4; mt++) {
                int row = wm + mt * 16 + a_row;
                int kg  = ks * 2 + a_kg;
                LDSM4(a[mt][0], a[mt][1], a[mt][2], a[mt][3], sA + swz(row, kg));
            }
            uint32_t b[4][2];
            #pragma unroll
            for (int pr = 0; pr < 2; pr++) {
                int row = wn + (pr * 2 + b_j) * 8 + b_row;
                int kg  = ks * 2 + b_half;
                uint32_t r0, r1, r2, r3;
                LDSM4(r0, r1, r2, r3, sBs + swz(row, kg));
                b[pr*2][0] = r0; b[pr*2][1] = r1;
                b[pr*2+1][0] = r2; b[pr*2+1][1] = r3;
            }
            #pragma unroll
            for (int mt = 0; mt < 4; mt++)
                #pragma unroll
                for (int nt = 0; nt < 4; nt++)
                    MMAF16A(cfr[mt][nt], a[mt], b[nt]);
        }
        __syncthreads();
    }
}

// Fused QKV projection, fp16 single-pass.
__global__ void __launch_bounds__(256) gemm_qkv16(float qscale)
{
    extern __shared__ char dsm[];
    const uint32_t sb = smem_u32(dsm);

    const int seg = blockIdx.x >> 3;
    const int bn  = (blockIdx.x & 7) * 128;
    const int bm  = blockIdx.y * 128;

    const __half* A = (seg == 0) ? g_qa16 : (seg == 1) ? g_ka16 : g_va16;
    const __half* W = (seg == 0) ? g_wq16 : (seg == 1) ? g_wk16 : g_wv16;
    __half* Hout    = (seg == 0) ? g_qh16 : (seg == 1) ? g_kh16 : g_vh16;
    const float scale = (seg == 0) ? qscale : 1.0f;

    float cfr[4][4][4];
    gemm_core16((const char*)(A + (size_t)bm * KFP),
                (const char*)(W + (size_t)bn * KFP), sb, cfr);

    const int lane = threadIdx.x & 31;
    const int wid  = threadIdx.x >> 5;
    const int wm   = (wid & 1) * 64;
    const int wn   = (wid >> 1) * 32;
    const int r0   = lane >> 2;
    const int cc0  = (lane & 3) * 2;
    #pragma unroll
    for (int mt = 0; mt < 4; mt++) {
        #pragma unroll
        for (int nt = 0; nt < 4; nt++) {
            int m = bm + wm + mt * 16 + r0;
            int n = bn + wn + nt * 8 + cc0;
            int bb = m >> 11, s = m & 2047, h = n >> 6, dh = n & 63;
            __half* d0 = Hout + (((size_t)(bb * HH + h) * SS + s) * DHD + dh);
            *(__half2*)d0 = __floats2half2_rn(cfr[mt][nt][0]*scale, cfr[mt][nt][1]*scale);
            *(__half2*)(d0 + 8 * DHD) = __floats2half2_rn(cfr[mt][nt][2]*scale, cfr[mt][nt][3]*scale);
        }
    }
}

// O-projection, fp16 single-pass, flat f32 out.
__global__ void __launch_bounds__(256) gemm_out16(float* __restrict__ f32dst)
{
    extern __shared__ char dsm[];
    const uint32_t sb = smem_u32(dsm);

    const int bn = blockIdx.x * 128;
    const int bm = blockIdx.y * 128;

    float cfr[4][4][4];
    gemm_core16((const char*)(g_o16 + (size_t)bm * KFP),
                (const char*)(g_wo16 + (size_t)bn * KFP), sb, cfr);

    const int lane = threadIdx.x & 31;
    const int wid  = threadIdx.x >> 5;
    const int wm   = (wid & 1) * 64;
    const int wn   = (wid >> 1) * 32;
    const int r0   = lane >> 2;
    const int cc0  = (lane & 3) * 2;
    #pragma unroll
    for (int mt = 0; mt < 4; mt++) {
        #pragma unroll
        for (int nt = 0; nt < 4; nt++) {
            int m = bm + wm + mt * 16 + r0;
            int n = bn + wn + nt * 8 + cc0;
            float* d0 = f32dst + (size_t)m * DD + n;
            *(float2*)d0 = make_float2(cfr[mt][nt][0], cfr[mt][nt][1]);
            *(float2*)(d0 + 8 * DD) = make_float2(cfr[mt][nt][2], cfr[mt][nt][3]);
        }
    }
}

// ---------------------------------------------------------------------------
// Tensor-core flash attention — R16 fragment math with 128-key software-
// pipelined iterations: QK(A), softmax(A), QK(B), PV(A), softmax(B), PV(B).
// Softmax(B)'s dependency stall is hidden behind PV(A)'s MMAs. One barrier
// per 128 keys. 4-buffer ring, pair-wise prefetch.
// ---------------------------------------------------------------------------
#define AT_NIT2 (SS/128)        // 16 iterations of 128 keys
#define AT_KV_STG 16384
#define ATTN_SMEM (16384 + 4*AT_KV_STG)   // 81920
#define AT_THREADS 128

__global__ void __launch_bounds__(AT_THREADS) attn_mma()
{
    extern __shared__ char smA[];
    const uint32_t sQ  = smem_u32(smA);
    const uint32_t sKV = sQ + 16384;

    const int tid  = threadIdx.x;
    const int lane = tid & 31;
    const int wrp  = tid >> 5;
    const int bh   = blockIdx.y;
    const int qm0  = blockIdx.x * 128;

    const char* Qg = (const char*)g_qh16 + ((size_t)bh * SS + qm0) * 128;
    const char* Kg = (const char*)g_kh16 + (size_t)bh * SS * 128;
    const char* Vg = (const char*)g_vh16 + (size_t)bh * SS * 128;

    int kv_isV[8], kv_row[8], kv_g[8];
    #pragma unroll
    for (int i = 0; i < 8; i++) {
        int G = tid + i * AT_THREADS;
        kv_isV[i] = G >> 9;
        int g = G & 511;
        kv_row[i] = g >> 3;
        kv_g[i]   = g & 7;
    }

    // per-thread prefetch of one 64-key subtile st into buffer st&3
    auto load_subtile = [&](int st_) {
        const uint32_t bufb = sKV + (st_ & 3) * AT_KV_STG;
        #pragma unroll
        for (int i = 0; i < 8; i++) {
            uint32_t dst = bufb + (kv_isV[i] ? 8192u : 0u) + swz8(kv_row[i], kv_g[i]);
            const char* src = (kv_isV[i] ? Vg : Kg)
                            + (size_t)(st_ * 64 + kv_row[i]) * 128 + kv_g[i] * 16;
            CP_ASYNC16(dst, src);
        }
    };

    // prologue: Q + subtiles 0,1 — single group
    #pragma unroll
    for (int i = 0; i < 8; i++) {
        int G = tid + i * AT_THREADS;
        int r = G >> 3, g = G & 7;
        CP_ASYNC16(sQ + swz8(r, g), Qg + r * 128 + g * 16);
    }
    load_subtile(0);
    load_subtile(1);
    CP_COMMIT();

    uint32_t qa[2][4][4];
    float oacc[2][8][4];
    #pragma unroll
    for (int mt = 0; mt < 2; mt++)
        #pragma unroll
        for (int nt = 0; nt < 8; nt++)
            #pragma unroll
            for (int j = 0; j < 4; j++) oacc[mt][nt][j] = 0.f;
    float lacc[2][4] = {{0.f,0.f,0.f,0.f},{0.f,0.f,0.f,0.f}};

    const int aq_row0 = wrp * 32 + (lane & 15);
    const int aq_kg   = lane >> 4;
    const int kb_sub  = lane >> 4;
    const int kb_half = (lane >> 3) & 1;
    const int kb_row  = lane & 7;
    const int vb_rsub = (lane >> 3) & 1;
    const int vb_row  = lane & 7;
    const int vb_gsub = lane >> 4;
    const uint32_t HONES = 0x3C003C00u;

    // ---- subtile compute pieces (R16-verified fragment math) ----
    auto qk_tile = [&](uint32_t sK, float (&sc)[2][8][4]) {
        #pragma unroll
        for (int mt = 0; mt < 2; mt++)
            #pragma unroll
            for (int nt = 0; nt < 8; nt++)
                #pragma unroll
                for (int j = 0; j < 4; j++) sc[mt][nt][j] = 0.f;
        #pragma unroll
        for (int ks = 0; ks < 4; ks++) {
            #pragma unroll
            for (int pr = 0; pr < 4; pr++) {
                int row = (pr * 2 + kb_sub) * 8 + kb_row;
                uint32_t b0, b1, b2, b3;
                LDSM4(b0, b1, b2, b3, sK + swz8(row, ks * 2 + kb_half));
                #pragma unroll
                for (int mt = 0; mt < 2; mt++) {
                    MMAFP16(sc[mt][pr*2],   qa[mt][ks][0], qa[mt][ks][1],
                            qa[mt][ks][2], qa[mt][ks][3], b0, b1);
                    MMAFP16(sc[mt][pr*2+1], qa[mt][ks][0], qa[mt][ks][1],
                            qa[mt][ks][2], qa[mt][ks][3], b2, b3);
                }
            }
        }
    };

    auto softmax_tile = [&](float (&sc)[2][8][4], uint32_t (&pa)[2][4][4]) {
        #pragma unroll
        for (int mt = 0; mt < 2; mt++) {
            #pragma unroll
            for (int ks = 0; ks < 4; ks++) {
                __half2 h0 = __floats2half2_rn(sc[mt][2*ks][0],   sc[mt][2*ks][1]);
                __half2 h1 = __floats2half2_rn(sc[mt][2*ks][2],   sc[mt][2*ks][3]);
                __half2 h2 = __floats2half2_rn(sc[mt][2*ks+1][0], sc[mt][2*ks+1][1]);
                __half2 h3 = __floats2half2_rn(sc[mt][2*ks+1][2], sc[mt][2*ks+1][3]);
                pa[mt][ks][0] = *(uint32_t*)&h0; pa[mt][ks][1] = *(uint32_t*)&h1;
                pa[mt][ks][2] = *(uint32_t*)&h2; pa[mt][ks][3] = *(uint32_t*)&h3;
                EX2H2(pa[mt][ks][0]); EX2H2(pa[mt][ks][1]);
                EX2H2(pa[mt][ks][2]); EX2H2(pa[mt][ks][3]);
                MMAFP16(lacc[mt], pa[mt][ks][0], pa[mt][ks][1],
                        pa[mt][ks][2], pa[mt][ks][3], HONES, HONES);
            }
        }
    };

    auto pv_tile = [&](uint32_t sV, uint32_t (&pa)[2][4][4]) {
        #pragma unroll
        for (int ks = 0; ks < 4; ks++) {
            #pragma unroll
            for (int pr = 0; pr < 4; pr++) {
                int row = ks * 16 + vb_rsub * 8 + vb_row;
                int g   = pr * 2 + vb_gsub;
                uint32_t b0, b1, b2, b3;
                LDSM4T(b0, b1, b2, b3, sV + swz8(row, g));
                #pragma unroll
                for (int mt = 0; mt < 2; mt++) {
                    MMAFP16(oacc[mt][pr*2],   pa[mt][ks][0], pa[mt][ks][1],
                            pa[mt][ks][2], pa[mt][ks][3], b0, b1);
                    MMAFP16(oacc[mt][pr*2+1], pa[mt][ks][0], pa[mt][ks][1],
                            pa[mt][ks][2], pa[mt][ks][3], b2, b3);
                }
            }
        }
    };

    #pragma unroll 1
    for (int it = 0; it < AT_NIT2; it++) {
        CP_WAIT0();          // this iteration's pair (and Q on it=0) resident
        __syncthreads();     // all threads' copies visible; prev pair free

        // prefetch next pair into the buffers freed by iteration it-1
        if (it + 1 < AT_NIT2) {
            load_subtile(2 * it + 2);
            load_subtile(2 * it + 3);
        }
        CP_COMMIT();

        if (it == 0) {
            #pragma unroll
            for (int mt = 0; mt < 2; mt++)
                #pragma unroll
                for (int ks = 0; ks < 4; ks++)
                    LDSM4(qa[mt][ks][0], qa[mt][ks][1], qa[mt][ks][2], qa[mt][ks][3],
                          sQ + swz8(aq_row0 + mt * 16, ks * 2 + aq_kg));
        }

        const uint32_t bA = sKV + ((2 * it)     & 3) * AT_KV_STG;
        const uint32_t bB = sKV + ((2 * it + 1) & 3) * AT_KV_STG;

        float sc[2][8][4];
        uint32_t paA[2][4][4], paB[2][4][4];

        qk_tile(bA, sc);                 // scores A
        softmax_tile(sc, paA);           // softmax A (stalls on QK(A))
        qk_tile(bB, sc);                 // scores B issued early
        pv_tile(bA + 8192, paA);         // PV A — covers QK(B) latency
        softmax_tile(sc, paB);           // softmax B — no stall
        pv_tile(bB + 8192, paB);         // PV B
    }

    // ---- epilogue: normalize, write fp16 flat [m, 1024] ----
    const int b = bh >> 4;
    const int h = bh & 15;
    const int cbase = h * DHD + (lane & 3) * 2;
    #pragma unroll
    for (int mt = 0; mt < 2; mt++) {
        const float inv0 = 1.0f / lacc[mt][0], inv1 = 1.0f / lacc[mt][2];
        const int m_r0 = qm0 + wrp * 32 + mt * 16 + (lane >> 2);
        __half* o0 = g_o16 + ((size_t)(b * SS + m_r0)) * KFP + cbase;
        __half* o1 = o0 + (size_t)8 * KFP;
        #pragma unroll
        for (int nt = 0; nt < 8; nt++) {
            *(__half2*)(o0 + nt * 8) =
                __floats2half2_rn(oacc[mt][nt][0] * inv0, oacc[mt][nt][1] * inv0);
            *(__half2*)(o1 + nt * 8) =
                __floats2half2_rn(oacc[mt][nt][2] * inv1, oacc[mt][nt][3] * inv1);
        }
    }
}

// ---------------------------------------------------------------------------
extern "C" void kernel_launch(void* const* d_in, const int* in_sizes, int n_in,
                              void* d_out, int out_size)
{
    const float* q  = (const float*)d_in[0];
    const float* k  = (const float*)d_in[1];
    const float* v  = (const float*)d_in[2];
    const float* Wq = (const float*)d_in[3];
    const float* Wk = (const float*)d_in[4];
    const float* Wv = (const float*)d_in[5];
    const float* Wo = (const float*)d_in[6];
    float* out = (float*)d_out;

    __half *qa16, *ka16, *va16, *wq16, *wk16, *wv16, *wo16;
    cudaGetSymbolAddress((void**)&qa16, g_qa16);
    cudaGetSymbolAddress((void**)&ka16, g_ka16);
    cudaGetSymbolAddress((void**)&va16, g_va16);
    cudaGetSymbolAddress((void**)&wq16, g_wq16);
    cudaGetSymbolAddress((void**)&wk16, g_wk16);
    cudaGetSymbolAddress((void**)&wv16, g_wv16);
    cudaGetSymbolAddress((void**)&wo16, g_wo16);

    cudaFuncSetAttribute(gemm_qkv16, cudaFuncAttributeMaxDynamicSharedMemorySize, GEMM_SMEM);
    cudaFuncSetAttribute(gemm_out16, cudaFuncAttributeMaxDynamicSharedMemorySize, GEMM_SMEM);
    cudaFuncSetAttribute(attn_mma, cudaFuncAttributeMaxDynamicSharedMemorySize, ATTN_SMEM);

    dim3 ca(MM, 3), cw(DD, 4);
    cvt16x3<<<ca, 256>>>((const float4*)q, (const float4*)k, (const float4*)v,
                         qa16, ka16, va16);
    cvt16x4<<<cw, 256>>>((const float4*)Wq, (const float4*)Wk,
                         (const float4*)Wv, (const float4*)Wo,
                         wq16, wk16, wv16, wo16);

    const float qscale = 0.125f * 1.44269504f;
    dim3 gqkv(24, MM / 128);
    gemm_qkv16<<<gqkv, 256, GEMM_SMEM>>>(qscale);

    dim3 ga(SS / 128, BB * HH);
    attn_mma<<<ga, AT_THREADS, ATTN_SMEM>>>();

    dim3 go(DD / 128, MM / 128);
    gemm_out16<<<go, 256, GEMM_SMEM>>>(out);
}